// round 3
// baseline (speedup 1.0000x reference)
#include <cuda_runtime.h>
#include <cstdint>

// DurationCalculator: B=256, Y=4096, X=1024
//   weights_argmax[b,y] = duration[b,y] + (y < output_length[b] ? 0 : -10000)
//   durations[b,x]      = #{ y < output_length[b] : duration[b,y] == x }
// duration values are in [0, X), so every valid element lands in range and
// every masked element falls below 0 (dropped by the reference's clip bucket).
//
// Output dtype is float32. Layout: [B*Y weights_argmax][B*X durations].
//
// Strategy: no shared-memory histogram. Hist bins get only ~2-4 increments
// each (uniform values), so direct global float atomicAdd (RED.F32, no-return)
// through the 184-partition L2 beats per-SM smem ATOMS serialization, and
// removes both barriers and the flush pass. Counts are small integers, so
// float accumulation is exact and order-independent (deterministic).

#define B_DIM 256
#define Y_DIM 4096
#define X_DIM 1024
#define MASK_PENALTY (-10000)

// 1024 int4 per row; grid covers B*Y/4 = 262144 int4s with 1024 CTAs x 256 thr.
__global__ __launch_bounds__(256, 8)
void duration_calc_kernel(const int* __restrict__ duration,
                          const int* __restrict__ output_length,
                          float* __restrict__ weights_out,
                          float* __restrict__ hist_out)
{
    const int gid = blockIdx.x * 256 + threadIdx.x;   // int4 index, 0..262143
    const int b   = gid >> 10;                        // 1024 int4 per row
    const int y0  = (gid & 1023) * 4;                 // element offset in row

    const int len = __ldg(&output_length[b]);

    const int4 v = reinterpret_cast<const int4*>(duration)[gid];

    const bool v0 = (y0 + 0) < len;
    const bool v1 = (y0 + 1) < len;
    const bool v2 = (y0 + 2) < len;
    const bool v3 = (y0 + 3) < len;

    float4 w;
    w.x = (float)(v.x + (v0 ? 0 : MASK_PENALTY));
    w.y = (float)(v.y + (v1 ? 0 : MASK_PENALTY));
    w.z = (float)(v.z + (v2 ? 0 : MASK_PENALTY));
    w.w = (float)(v.w + (v3 ? 0 : MASK_PENALTY));

    reinterpret_cast<float4*>(weights_out)[gid] = w;

    float* hrow = hist_out + (size_t)b * X_DIM;
    if (v0) atomicAdd(&hrow[v.x], 1.0f);
    if (v1) atomicAdd(&hrow[v.y], 1.0f);
    if (v2) atomicAdd(&hrow[v.z], 1.0f);
    if (v3) atomicAdd(&hrow[v.w], 1.0f);
}

extern "C" void kernel_launch(void* const* d_in, const int* in_sizes, int n_in,
                              void* d_out, int out_size)
{
    const int* duration      = (const int*)d_in[0];   // (B, Y) int32
    const int* output_length = (const int*)d_in[1];   // (B,)   int32
    // d_in[2] (x_steps) is the compile-time constant X_DIM = 1024.

    float* weights_out = (float*)d_out;                         // B*Y floats
    float* hist_out    = (float*)d_out + (size_t)B_DIM * Y_DIM; // B*X floats

    // Zero the histogram region (graph-capturable memset node).
    cudaMemsetAsync(hist_out, 0, (size_t)B_DIM * X_DIM * sizeof(float), 0);

    duration_calc_kernel<<<(B_DIM * Y_DIM / 4) / 256, 256>>>(
        duration, output_length, weights_out, hist_out);
}

// round 4
// speedup vs baseline: 1.2694x; 1.2694x over previous
#include <cuda_runtime.h>
#include <cstdint>

// DurationCalculator: B=256, Y=4096, X=1024
//   weights_argmax[b,y] = duration[b,y] + (y < output_length[b] ? 0 : -10000)
//   durations[b,x]      = #{ y < output_length[b] : duration[b,y] == x }
// duration values are in [0, X): all valid elements in range, all masked
// elements drop below 0 (reference clips them into the discarded bucket).
//
// Output dtype float32. Layout: [B*Y weights_argmax][B*X durations].
//
// Two-phase design:
//  Phase 1: 512 CTAs (2 per row, 512 threads). Each CTA histograms its
//           half-row into a private smem int histogram (ATOMS spread ~2cyc/ln;
//           worst chain halved vs one-CTA-per-row) and writes the masked
//           weights (1 int4 load + 1 float4 store per thread). Partial hist
//           stored non-atomically to __device__ scratch.
//  Phase 2: tiny streaming kernel sums the two partials per row -> float.

#define B_DIM 256
#define Y_DIM 4096
#define X_DIM 1024
#define MASK_PENALTY (-10000)

__device__ int g_partial[2 * B_DIM * X_DIM];   // 2 MiB scratch, 512 partial hists

__global__ __launch_bounds__(512, 4)
void duration_phase1(const int* __restrict__ duration,
                     const int* __restrict__ output_length,
                     float* __restrict__ weights_out)
{
    __shared__ int hist[X_DIM];

    const int bid  = blockIdx.x;       // 0..511
    const int row  = bid >> 1;
    const int half = bid & 1;
    const int tid  = threadIdx.x;      // 0..511

    hist[tid]       = 0;
    hist[tid + 512] = 0;
    __syncthreads();

    const int len = __ldg(&output_length[row]);

    // Half-row = 2048 ints = 512 int4s; one int4 per thread.
    const int gid4 = row * (Y_DIM / 4) + half * 512 + tid;
    const int y0   = (half * 512 + tid) * 4;

    const int4 v = reinterpret_cast<const int4*>(duration)[gid4];

    const bool m0 = (y0 + 0) < len;
    const bool m1 = (y0 + 1) < len;
    const bool m2 = (y0 + 2) < len;
    const bool m3 = (y0 + 3) < len;

    float4 w;
    w.x = (float)(v.x + (m0 ? 0 : MASK_PENALTY));
    w.y = (float)(v.y + (m1 ? 0 : MASK_PENALTY));
    w.z = (float)(v.z + (m2 ? 0 : MASK_PENALTY));
    w.w = (float)(v.w + (m3 ? 0 : MASK_PENALTY));

    reinterpret_cast<float4*>(weights_out)[gid4] = w;

    if (m0) atomicAdd(&hist[v.x], 1);
    if (m1) atomicAdd(&hist[v.y], 1);
    if (m2) atomicAdd(&hist[v.z], 1);
    if (m3) atomicAdd(&hist[v.w], 1);

    __syncthreads();

    // Coalesced non-atomic partial flush (int4 = 4 bins per thread... 1024/512=2)
    int* dst = g_partial + (size_t)bid * X_DIM;
    dst[tid]       = hist[tid];
    dst[tid + 512] = hist[tid + 512];
}

__global__ __launch_bounds__(256, 8)
void duration_phase2(float* __restrict__ hist_out)
{
    // 256 CTAs x 256 thr, 4 bins per thread (int4): covers B*X = 256K bins.
    const int t   = blockIdx.x * 256 + threadIdx.x;  // int4-group id
    const int row = t >> 8;                          // 256 int4 groups per row
    const int g   = t & 255;

    const int4 a = reinterpret_cast<const int4*>(g_partial + (size_t)(2 * row) * X_DIM)[g];
    const int4 b = reinterpret_cast<const int4*>(g_partial + (size_t)(2 * row + 1) * X_DIM)[g];

    float4 o;
    o.x = (float)(a.x + b.x);
    o.y = (float)(a.y + b.y);
    o.z = (float)(a.z + b.z);
    o.w = (float)(a.w + b.w);

    reinterpret_cast<float4*>(hist_out + (size_t)row * X_DIM)[g] = o;
}

extern "C" void kernel_launch(void* const* d_in, const int* in_sizes, int n_in,
                              void* d_out, int out_size)
{
    const int* duration      = (const int*)d_in[0];   // (B, Y) int32
    const int* output_length = (const int*)d_in[1];   // (B,)   int32
    // d_in[2] (x_steps) is the compile-time constant X_DIM = 1024.

    float* weights_out = (float*)d_out;                         // B*Y floats
    float* hist_out    = (float*)d_out + (size_t)B_DIM * Y_DIM; // B*X floats

    duration_phase1<<<2 * B_DIM, 512>>>(duration, output_length, weights_out);
    duration_phase2<<<B_DIM, 256>>>(hist_out);
}